// round 1
// baseline (speedup 1.0000x reference)
#include <cuda_runtime.h>

#define HWC   65536   // H*W = 256*256
#define WDIM  256
#define NKPT  68
#define OFF_SCALE 6.0f
#define MAXB  256

// Per-batch transform scratch: R (9, row-major, already scaled by sd2/sd1) then T (3)
__device__ float g_RT[MAXB][12];

// ---------------------------------------------------------------------------
// 3x3 inverse via adjugate
// ---------------------------------------------------------------------------
__device__ __forceinline__ void inv3(const float M[9], float Inv[9]) {
    float a = M[0], b = M[1], c = M[2];
    float d = M[3], e = M[4], f = M[5];
    float g = M[6], h = M[7], i = M[8];
    float c0 = e * i - f * h;
    float c3 = f * g - d * i;
    float c6 = d * h - e * g;
    float det = a * c0 + b * c3 + c * c6;
    float inv_det = 1.0f / det;
    Inv[0] = c0 * inv_det;
    Inv[1] = (c * h - b * i) * inv_det;
    Inv[2] = (b * f - c * e) * inv_det;
    Inv[3] = c3 * inv_det;
    Inv[4] = (a * i - c * g) * inv_det;
    Inv[5] = (c * d - a * f) * inv_det;
    Inv[6] = c6 * inv_det;
    Inv[7] = (b * g - a * h) * inv_det;
    Inv[8] = (a * e - b * d) * inv_det;
}

// Block-wide sum over 128 threads
__device__ __forceinline__ float blockSum(float v, float* red, int tid) {
    __syncthreads();
    red[tid] = v;
    __syncthreads();
    #pragma unroll
    for (int s = 64; s > 0; s >>= 1) {
        if (tid < s) red[tid] += red[tid + s];
        __syncthreads();
    }
    return red[0];
}

// ---------------------------------------------------------------------------
// Kernel 1: one block per batch. Gather keypoints, build similarity-normalized
// cross-covariance H, compute R = polar(H^T) via scaled Newton, store R*ratio, T.
// ---------------------------------------------------------------------------
__global__ void prep_kernel(const float* __restrict__ Off,
                            const float* __restrict__ Pos,
                            const float* __restrict__ mean,
                            const int*   __restrict__ uv) {
    __shared__ float s_src[NKPT * 3];
    __shared__ float s_dst[NKPT * 3];
    __shared__ float s_red[128];
    __shared__ int   s_is32;

    const int tid = threadIdx.x;
    const int b   = blockIdx.x;

    // --- detect int32 vs int64 uv_kpt layout (values are in [0,256)) ---
    if (tid == 0) s_is32 = 0;
    __syncthreads();
    for (int i = tid; i < NKPT; i += 128) {
        // odd 32-bit words: int64 -> high words (all zero); int32 -> real coords
        if (uv[2 * i + 1] != 0) s_is32 = 1;
    }
    __syncthreads();
    const int is32 = s_is32;

    // --- gather 68 keypoints ---
    if (tid < NKPT) {
        int u, v;
        if (is32) { u = uv[2 * tid];     v = uv[2 * tid + 1]; }
        else      { u = uv[4 * tid];     v = uv[4 * tid + 2]; }
        const int p = u * WDIM + v;
        const float* ob = Off + (size_t)b * 3 * HWC;
        const float* pb = Pos + (size_t)b * 3 * HWC;
        #pragma unroll
        for (int c = 0; c < 3; c++) {
            s_src[tid * 3 + c] = fmaf(ob[c * HWC + p], OFF_SCALE, mean[c * HWC + p]);
            s_dst[tid * 3 + c] = pb[c * HWC + p];
        }
    }
    __syncthreads();

    const float cs0 = s_src[33 * 3 + 0], cs1 = s_src[33 * 3 + 1], cs2 = s_src[33 * 3 + 2];
    const float cd0 = s_dst[33 * 3 + 0], cd1 = s_dst[33 * 3 + 1], cd2 = s_dst[33 * 3 + 2];

    float ms0 = 0.f, ms1 = 0.f, ms2 = 0.f;
    float md0 = 0.f, md1 = 0.f, md2 = 0.f;
    float n1 = 0.f, n2 = 0.f;
    if (tid < NKPT) {
        ms0 = s_src[tid * 3 + 0]; ms1 = s_src[tid * 3 + 1]; ms2 = s_src[tid * 3 + 2];
        md0 = s_dst[tid * 3 + 0]; md1 = s_dst[tid * 3 + 1]; md2 = s_dst[tid * 3 + 2];
        float dx = ms0 - cs0, dy = ms1 - cs1, dz = ms2 - cs2;
        n1 = sqrtf(dx * dx + dy * dy + dz * dz);
        dx = md0 - cd0; dy = md1 - cd1; dz = md2 - cd2;
        n2 = sqrtf(dx * dx + dy * dy + dz * dz);
    }

    const float sd1 = blockSum(n1, s_red, tid);
    const float sd2 = blockSum(n2, s_red, tid);

    float ssum[3], dsum[3];
    ssum[0] = blockSum(ms0, s_red, tid);
    ssum[1] = blockSum(ms1, s_red, tid);
    ssum[2] = blockSum(ms2, s_red, tid);
    dsum[0] = blockSum(md0, s_red, tid);
    dsum[1] = blockSum(md1, s_red, tid);
    dsum[2] = blockSum(md2, s_red, tid);

    const float msv[3] = {ms0, ms1, ms2};
    const float mdv[3] = {md0, md1, md2};
    float SD[9];
    #pragma unroll
    for (int i = 0; i < 3; i++)
        #pragma unroll
        for (int j = 0; j < 3; j++)
            SD[i * 3 + j] = blockSum(msv[i] * mdv[j], s_red, tid);

    if (tid == 0) {
        const float ratio = sd2 / sd1;
        const float invn  = 1.0f / (float)NKPT;
        // H[i][j] = ratio * (SD[i][j] - ssum[i]*dsum[j]/n);  then M = H^T
        float X[9];
        #pragma unroll
        for (int i = 0; i < 3; i++)
            #pragma unroll
            for (int j = 0; j < 3; j++)
                X[j * 3 + i] = ratio * (SD[i * 3 + j] - ssum[i] * dsum[j] * invn);

        // Scaled Newton polar iteration: X -> orthogonal polar factor of H^T = V U^T
        #pragma unroll 1
        for (int it = 0; it < 14; it++) {
            float Xi[9];
            inv3(X, Xi);
            float nx = 0.f, ni = 0.f;
            #pragma unroll
            for (int k = 0; k < 9; k++) { nx += X[k] * X[k]; ni += Xi[k] * Xi[k]; }
            float z  = sqrtf(sqrtf(ni / nx));   // (||Xi||_F / ||X||_F)^(1/2)
            float zh = 0.5f * z;
            float zi = 0.5f / z;
            float Y[9];
            #pragma unroll
            for (int i = 0; i < 3; i++)
                #pragma unroll
                for (int j = 0; j < 3; j++)
                    Y[i * 3 + j] = zh * X[i * 3 + j] + zi * Xi[j * 3 + i];
            #pragma unroll
            for (int k = 0; k < 9; k++) X[k] = Y[k];
        }

        // T[j] = mean(dst)[j] - sum_i (ratio*mean(src)[i]) * R0[j][i]
        float Am[3], Bm[3];
        #pragma unroll
        for (int c = 0; c < 3; c++) {
            Am[c] = ratio * ssum[c] * invn;
            Bm[c] = dsum[c] * invn;
        }
        #pragma unroll
        for (int k = 0; k < 9; k++) g_RT[b][k] = ratio * X[k];
        #pragma unroll
        for (int j = 0; j < 3; j++)
            g_RT[b][9 + j] = Bm[j] - (Am[0] * X[j * 3 + 0] + Am[1] * X[j * 3 + 1] + Am[2] * X[j * 3 + 2]);
    }
}

// ---------------------------------------------------------------------------
// Kernel 2: streaming transform. out[b,j,p] = sum_i Rs[j,i]*(Off[b,i,p]*6+mean[i,p]) + T[j]
// float4 vectorized; mean stays L2-resident across batches.
// ---------------------------------------------------------------------------
__global__ void __launch_bounds__(256) transform_kernel(
        const float* __restrict__ Off,
        const float* __restrict__ mean,
        float* __restrict__ out) {
    const int b = blockIdx.y;
    const int p = blockIdx.x * blockDim.x + threadIdx.x;  // float4 index, [0, HWC/4)
    const int Q = HWC / 4;

    const float* rt = g_RT[b];
    const float r00 = rt[0], r01 = rt[1], r02 = rt[2];
    const float r10 = rt[3], r11 = rt[4], r12 = rt[5];
    const float r20 = rt[6], r21 = rt[7], r22 = rt[8];
    const float t0  = rt[9], t1  = rt[10], t2 = rt[11];

    const float4* o  = (const float4*)(Off + (size_t)b * 3 * HWC);
    const float4* m  = (const float4*)mean;
    float4*       ob = (float4*)(out + (size_t)b * 3 * HWC);

    float4 a0 = o[p], a1 = o[p + Q], a2 = o[p + 2 * Q];
    float4 m0 = m[p], m1 = m[p + Q], m2 = m[p + 2 * Q];
    float4 y0, y1, y2;

#define COMP(f)                                                         \
    {                                                                   \
        float c0 = fmaf(a0.f, OFF_SCALE, m0.f);                         \
        float c1 = fmaf(a1.f, OFF_SCALE, m1.f);                         \
        float c2 = fmaf(a2.f, OFF_SCALE, m2.f);                         \
        y0.f = fmaf(r00, c0, fmaf(r01, c1, fmaf(r02, c2, t0)));         \
        y1.f = fmaf(r10, c0, fmaf(r11, c1, fmaf(r12, c2, t1)));         \
        y2.f = fmaf(r20, c0, fmaf(r21, c1, fmaf(r22, c2, t2)));         \
    }
    COMP(x) COMP(y) COMP(z) COMP(w)
#undef COMP

    ob[p]         = y0;
    ob[p + Q]     = y1;
    ob[p + 2 * Q] = y2;
}

extern "C" void kernel_launch(void* const* d_in, const int* in_sizes, int n_in,
                              void* d_out, int out_size) {
    const float* Off  = (const float*)d_in[0];
    const float* Pos  = (const float*)d_in[1];
    const float* mean = (const float*)d_in[2];
    const int*   uv   = (const int*)d_in[3];

    int nb = in_sizes[0] / (3 * HWC);
    if (nb > MAXB) nb = MAXB;

    prep_kernel<<<nb, 128>>>(Off, Pos, mean, uv);

    dim3 grid(HWC / 4 / 256, nb);   // (64, nb)
    transform_kernel<<<grid, 256>>>(Off, mean, (float*)d_out);
}